// round 6
// baseline (speedup 1.0000x reference)
#include <cuda_runtime.h>
#include <cuda_bf16.h>

// ---------------------------------------------------------------------------
// BiLSTM_55499567398998 — fused fp32, k-paired fma.rn.f32x2 implementation
//   B=1024, T=128, H1=50, H2=150
//   Layer-2 backward collapses to ONE step (head reads out2[:, -1] only).
//   lstm2: 1 gate/thread, 608 threads; weights k-pair packed so both f32x2
//   operands come packed from memory (no MOV duplication); streamed weights
//   in k-quad-major layout for fully-coalesced LDG (100% sector efficiency);
//   192 gate rows cached in smem at stride 260 (bank-conflict-free).
// ---------------------------------------------------------------------------

#define B_   1024
#define T_   128
#define H1_  50
#define G1_  200      // 4*H1
#define H2_  150
#define G2_  600      // 4*H2
#define KC_  256      // padded concat width [h(150) | x(100) | pad(6)]
#define GP_  608      // padded gate count (8 dummy gates)
#define R1_  8        // rows per block, layer 1
#define R2_  8        // rows per block, layer 2
#define NCW_ 192      // layer-2 gate rows cached in smem
#define WS_  260      // smem weight row stride in floats (conflict-free)
#define NKQ_ 64       // 256 k / 4

// scratch (device globals; no allocation at runtime)
__device__ float g_out1[B_ * T_ * 100];      // layer-1 output [b][t][ch]
__device__ float g_Wcat[G2_ * KC_];          // packed rows [Whh2_f | Wih2_f | 0]
__device__ float g_WQ  [NKQ_ * GP_ * 4];     // k-quad-major: [kq][j][4]
__device__ float g_h2f [B_ * H2_];           // layer-2 fwd final hidden

__device__ __forceinline__ float sigf(float z) { return 1.0f / (1.0f + __expf(-z)); }
__device__ __forceinline__ float lrelu(float z) { return z > 0.0f ? z : 0.3f * z; }

__device__ __forceinline__ unsigned long long pack2(float lo, float hi) {
    unsigned long long r;
    asm("mov.b64 %0, {%1, %2};" : "=l"(r) : "f"(lo), "f"(hi));
    return r;
}
__device__ __forceinline__ void fmaf2(unsigned long long& acc,
                                      unsigned long long a, unsigned long long b) {
    asm("fma.rn.f32x2 %0, %1, %2, %0;" : "+l"(acc) : "l"(a), "l"(b));
}
__device__ __forceinline__ float hsum2(unsigned long long v) {
    float lo, hi;
    asm("mov.b64 {%0, %1}, %2;" : "=f"(lo), "=f"(hi) : "l"(v));
    return lo + hi;
}

// ---------------------------------------------------------------------------
// K0: build g_Wcat (row-major, 256-wide) and g_WQ (k-quad-major, coalesced)
//   W[j][k] = Whh2f[j][k] (k<150) | Wih2f[j][k-150] (k<250) | 0
// ---------------------------------------------------------------------------
__global__ void prep_kernel(const float* __restrict__ Whh2f,
                            const float* __restrict__ Wih2f)
{
    int j = blockIdx.x;        // 608 blocks
    int k = threadIdx.x;       // 256 threads
    float v = 0.0f;
    if (j < G2_) {
        if (k < 150)       v = Whh2f[j * 150 + k];
        else if (k < 250)  v = Wih2f[j * 100 + (k - 150)];
        g_Wcat[j * KC_ + k] = v;
    }
    g_WQ[(k >> 2) * (GP_ * 4) + j * 4 + (k & 3)] = v;
}

// ---------------------------------------------------------------------------
// K1: layer-1 scan, both directions (blockIdx.y = dir), 8 rows per block.
//   Recurrent weights in registers as k-pairs; fma.rn.f32x2 over k.
// ---------------------------------------------------------------------------
__global__ void __launch_bounds__(256)
lstm1_kernel(const float* __restrict__ x,
             const float* __restrict__ Wih_f, const float* __restrict__ Whh_f,
             const float* __restrict__ b_f,
             const float* __restrict__ Wih_b, const float* __restrict__ Whh_b,
             const float* __restrict__ b_b)
{
    const int dir = blockIdx.y;
    const float* Wih = dir ? Wih_b : Wih_f;
    const float* Whh = dir ? Whh_b : Whh_f;
    const float* bv  = dir ? b_b  : b_f;
    const int row0 = blockIdx.x * R1_;
    const int tid  = threadIdx.x;

    __shared__ float h_s[R1_][H1_];     // row stride 200B: 8B-aligned pairs
    __shared__ float g_s[R1_][G1_];
    __shared__ float x_s[R1_][T_];

    for (int i = tid; i < R1_ * T_; i += 256)
        x_s[i / T_][i % T_] = x[(row0 + i / T_) * T_ + (i % T_)];
    for (int i = tid; i < R1_ * H1_; i += 256)
        h_s[i / H1_][i % H1_] = 0.0f;

    // per-gate recurrent weights as 25 k-pairs in registers
    unsigned long long wp[H1_ / 2];
    float wih_j = 0.0f, bj = 0.0f;
    if (tid < G1_) {
#pragma unroll
        for (int kk = 0; kk < H1_ / 2; kk++) {
            float2 wv = *(const float2*)&Whh[tid * H1_ + 2 * kk];
            wp[kk] = pack2(wv.x, wv.y);
        }
        wih_j = Wih[tid];
        bj    = bv[tid];
    }

    const int u0 = tid, u1 = tid + 256;        // update items (r,k), total 400
    const int r0 = u0 / H1_, k0 = u0 % H1_;
    const int r1 = u1 / H1_, k1 = u1 % H1_;
    float c0 = 0.0f, c1 = 0.0f;

    __syncthreads();

    for (int t = 0; t < T_; t++) {
        const int tt = dir ? (T_ - 1 - t) : t;

        if (tid < G1_) {
            unsigned long long acc[R1_];
#pragma unroll
            for (int r = 0; r < R1_; r++)
                acc[r] = pack2(fmaf(x_s[r][tt], wih_j, bj), 0.0f);
#pragma unroll
            for (int kk = 0; kk < H1_ / 2; kk++) {
#pragma unroll
                for (int r = 0; r < R1_; r++) {
                    unsigned long long hv = *(const unsigned long long*)&h_s[r][2 * kk];
                    fmaf2(acc[r], wp[kk], hv);
                }
            }
#pragma unroll
            for (int r = 0; r < R1_; r++) g_s[r][tid] = hsum2(acc[r]);
        }
        __syncthreads();

        {
            float i_ = g_s[r0][k0], f_ = g_s[r0][H1_ + k0];
            float gg = g_s[r0][2 * H1_ + k0], o_ = g_s[r0][3 * H1_ + k0];
            c0 = sigf(f_) * c0 + sigf(i_) * tanhf(gg);
            float h = sigf(o_) * tanhf(c0);
            h_s[r0][k0] = h;
            g_out1[(row0 + r0) * (T_ * 100) + tt * 100 + dir * H1_ + k0] = h;
        }
        if (u1 < 400) {
            float i_ = g_s[r1][k1], f_ = g_s[r1][H1_ + k1];
            float gg = g_s[r1][2 * H1_ + k1], o_ = g_s[r1][3 * H1_ + k1];
            c1 = sigf(f_) * c1 + sigf(i_) * tanhf(gg);
            float h = sigf(o_) * tanhf(c1);
            h_s[r1][k1] = h;
            g_out1[(row0 + r1) * (T_ * 100) + tt * 100 + dir * H1_ + k1] = h;
        }
        __syncthreads();
    }
}

// ---------------------------------------------------------------------------
// K2: layer-2 FORWARD scan.  128 blocks x 608 threads, 8 rows per block.
//   Thread j computes gate j for all 8 rows (k-paired f32x2 accumulate).
//   j < NCW_: weights from smem (stride 260, conflict-free LDS.128).
//   j >= NCW_: weights from g_WQ (k-quad-major, coalesced LDG.128).
// ---------------------------------------------------------------------------
#define SMEM2_BYTES ((NCW_ * WS_ + R2_ * KC_ + R2_ * GP_) * 4)   // 227,328 B

__global__ void __launch_bounds__(608, 1)
lstm2_kernel(const float* __restrict__ b2)
{
    extern __shared__ float sm[];
    float* w_c = sm;                                         // NCW_ * WS_
    float (*v_s)[KC_] = (float(*)[KC_])(sm + NCW_ * WS_);    // 8 x 256
    float (*g_s)[GP_] = (float(*)[GP_])(sm + NCW_ * WS_ + R2_ * KC_);

    const int tid  = threadIdx.x;
    const int row0 = blockIdx.x * R2_;

    // fill smem weight cache (first NCW_ rows, padded stride)
    for (int i = tid; i < NCW_ * KC_; i += 608)
        w_c[(i >> 8) * WS_ + (i & 255)] = g_Wcat[i];
    // zero v (covers pad lanes 250..255 permanently)
    for (int i = tid; i < R2_ * KC_; i += 608)
        ((float*)v_s)[i] = 0.0f;

    const int j  = tid;                       // gate (608, last 8 dummy)
    const float bj = (j < G2_) ? b2[j] : 0.0f;

    const int u0 = tid, u1 = tid + 608;       // update items, total 1200
    const int r0 = u0 / H2_, k0 = u0 % H2_;
    const int r1 = u1 / H2_, k1 = u1 % H2_;
    float c0 = 0.0f, c1 = 0.0f;

    __syncthreads();
    // prologue: x(t=0) into v_s[.][150..249]
    for (int i = tid; i < R2_ * 100; i += 608)
        v_s[i / 100][150 + i % 100] = g_out1[(row0 + i / 100) * (T_ * 100) + (i % 100)];
    __syncthreads();

    const float4* wq = (const float4*)g_WQ + j;          // stride GP_ per kq
    const ulonglong2* wsm = (const ulonglong2*)(w_c + j * WS_);

    for (int t = 0; t < T_; t++) {
        {
            unsigned long long acc[R2_];
#pragma unroll
            for (int r = 0; r < R2_; r++) acc[r] = pack2(bj, 0.0f);

            if (j < NCW_) {
#pragma unroll 4
                for (int kq = 0; kq < NKQ_; kq++) {
                    ulonglong2 w = wsm[kq];
#pragma unroll
                    for (int r = 0; r < R2_; r++) {
                        ulonglong2 v = *(const ulonglong2*)&v_s[r][kq * 4];
                        fmaf2(acc[r], w.x, v.x);
                        fmaf2(acc[r], w.y, v.y);
                    }
                }
            } else {
#pragma unroll 4
                for (int kq = 0; kq < NKQ_; kq++) {
                    float4 wf = wq[kq * GP_];            // coalesced LDG.128
                    ulonglong2 w = *(const ulonglong2*)&wf;
#pragma unroll
                    for (int r = 0; r < R2_; r++) {
                        ulonglong2 v = *(const ulonglong2*)&v_s[r][kq * 4];
                        fmaf2(acc[r], w.x, v.x);
                        fmaf2(acc[r], w.y, v.y);
                    }
                }
            }
#pragma unroll
            for (int r = 0; r < R2_; r++) g_s[r][j] = hsum2(acc[r]);
        }
        __syncthreads();

        {   // update item u0 (tid < 608 < 1200: always valid)
            float i_ = g_s[r0][k0],            f_ = g_s[r0][H2_ + k0];
            float gg = g_s[r0][2 * H2_ + k0],  o_ = g_s[r0][3 * H2_ + k0];
            c0 = sigf(f_) * c0 + sigf(i_) * tanhf(gg);
            v_s[r0][k0] = sigf(o_) * tanhf(c0);
        }
        if (u1 < R2_ * H2_) {
            float i_ = g_s[r1][k1],            f_ = g_s[r1][H2_ + k1];
            float gg = g_s[r1][2 * H2_ + k1],  o_ = g_s[r1][3 * H2_ + k1];
            c1 = sigf(f_) * c1 + sigf(i_) * tanhf(gg);
            v_s[r1][k1] = sigf(o_) * tanhf(c1);
        }
        if (t < T_ - 1) {  // prefetch x(t+1): lanes 150..249, disjoint from h
            for (int i = tid; i < R2_ * 100; i += 608)
                v_s[i / 100][150 + i % 100] =
                    g_out1[(row0 + i / 100) * (T_ * 100) + (t + 1) * 100 + (i % 100)];
        }
        __syncthreads();
    }

    for (int i = tid; i < R2_ * H2_; i += 608)
        g_h2f[(row0 + i / H2_) * H2_ + i % H2_] = v_s[i / H2_][i % H2_];
}

// ---------------------------------------------------------------------------
// K3: layer-2 backward (single step from h0=0 at t=T-1) + all heads.
// ---------------------------------------------------------------------------
__global__ void __launch_bounds__(256)
head_kernel(const float* __restrict__ Wih2b, const float* __restrict__ b2b,
            const float* __restrict__ rrs,
            const float* __restrict__ headW, const float* __restrict__ headb,
            const float* __restrict__ p1W,  const float* __restrict__ p1b,
            const float* __restrict__ p2W,  const float* __restrict__ p2b,
            const float* __restrict__ fcW,  const float* __restrict__ fcb,
            float* __restrict__ out)
{
    const int row = blockIdx.x;
    const int tid = threadIdx.x;
    __shared__ float in1[100];
    __shared__ float g2[G2_];
    __shared__ float net[300];
    __shared__ float feat_s[30];

    if (tid < 100) in1[tid] = g_out1[row * (T_ * 100) + (T_ - 1) * 100 + tid];
    for (int i = tid; i < H2_; i += 256) net[i] = g_h2f[row * H2_ + i];
    __syncthreads();

    for (int jj = tid; jj < G2_; jj += 256) {
        float a = b2b[jj];
        const float* w = Wih2b + jj * 100;
#pragma unroll
        for (int k = 0; k < 100; k++) a = fmaf(w[k], in1[k], a);
        g2[jj] = a;
    }
    __syncthreads();

    for (int k = tid; k < H2_; k += 256) {
        float i_ = g2[k], gg = g2[2 * H2_ + k], o_ = g2[3 * H2_ + k];
        float c = sigf(i_) * tanhf(gg);                 // sig(f)*c0 term = 0
        net[H2_ + k] = sigf(o_) * tanhf(c);
    }
    __syncthreads();

    if (tid < 20) {
        float a = headb[tid];
        const float* w = headW + tid * 300;
        for (int k = 0; k < 300; k++) a = fmaf(w[k], net[k], a);
        a = lrelu(a);
        feat_s[tid] = a;
        out[row * 20 + tid] = a;                        // waveform_feat
    }
    if (tid >= 32 && tid < 42) {
        int t = tid - 32;
        float a = p1b[t];
        for (int k = 0; k < 4; k++) a = fmaf(p1W[t * 4 + k], rrs[row * 4 + k], a);
        feat_s[20 + t] = lrelu(a);
    }
    __syncthreads();

    if (tid < 2) {
        float a = p2b[tid];
        for (int k = 0; k < 10; k++) a = fmaf(p2W[tid * 10 + k], feat_s[20 + k], a);
        out[B_ * 20 + row * 2 + tid] = a;               // pef_logits
    }
    if (tid < 30) out[B_ * 22 + row * 30 + tid] = feat_s[tid];   // feat
    if (tid < 4) {
        float a = fcb[tid];
        for (int k = 0; k < 30; k++) a = fmaf(fcW[tid * 30 + k], feat_s[k], a);
        out[B_ * 52 + row * 4 + tid] = a;               // logits
    }
}

// ---------------------------------------------------------------------------
extern "C" void kernel_launch(void* const* d_in, const int* in_sizes, int n_in,
                              void* d_out, int out_size)
{
    const float* x      = (const float*)d_in[0];
    const float* rrs    = (const float*)d_in[1];
    const float* l1Wihf = (const float*)d_in[2];
    const float* l1Whhf = (const float*)d_in[3];
    const float* l1bf   = (const float*)d_in[4];
    const float* l1Wihb = (const float*)d_in[5];
    const float* l1Whhb = (const float*)d_in[6];
    const float* l1bb   = (const float*)d_in[7];
    const float* l2Wihf = (const float*)d_in[8];
    const float* l2Whhf = (const float*)d_in[9];
    const float* l2bf   = (const float*)d_in[10];
    const float* l2Wihb = (const float*)d_in[11];
    /* d_in[12] = l2_Whh_b: unused — backward L2 is a single step from h0=0 */
    const float* l2bb   = (const float*)d_in[13];
    const float* headW  = (const float*)d_in[14];
    const float* headb  = (const float*)d_in[15];
    const float* p1W    = (const float*)d_in[16];
    const float* p1b    = (const float*)d_in[17];
    const float* p2W    = (const float*)d_in[18];
    const float* p2b    = (const float*)d_in[19];
    const float* fcW    = (const float*)d_in[20];
    const float* fcb    = (const float*)d_in[21];

    cudaFuncSetAttribute(lstm2_kernel,
                         cudaFuncAttributeMaxDynamicSharedMemorySize, SMEM2_BYTES);

    prep_kernel<<<GP_, KC_>>>(l2Whhf, l2Wihf);
    lstm1_kernel<<<dim3(B_ / R1_, 2), 256>>>(x, l1Wihf, l1Whhf, l1bf,
                                             l1Wihb, l1Whhb, l1bb);
    lstm2_kernel<<<B_ / R2_, 608, SMEM2_BYTES>>>(l2bf);
    head_kernel<<<B_, 256>>>(l2Wihb, l2bb, rrs, headW, headb,
                             p1W, p1b, p2W, p2b, fcW, fcb, (float*)d_out);
}

// round 8
// speedup vs baseline: 1.0465x; 1.0465x over previous
#include <cuda_runtime.h>
#include <cuda_bf16.h>

// ---------------------------------------------------------------------------
// BiLSTM_55499567398998 — fused fp32, k-paired fma.rn.f32x2 implementation
//   B=1024, T=128, H1=50, H2=150
//   Layer-2 backward collapses to ONE step (head reads out2[:, -1] only);
//   that step + all heads are fused into lstm2's epilogue (no head kernel).
//   tanh via overflow-safe __expf form (EX2+RCP), not libm tanhf.
// ---------------------------------------------------------------------------

#define B_   1024
#define T_   128
#define H1_  50
#define G1_  200      // 4*H1
#define H2_  150
#define G2_  600      // 4*H2
#define KC_  256      // padded concat width [h(150) | x(100) | pad(6)]
#define GP_  608      // padded gate count (8 dummy gates)
#define R1_  8        // rows per block, layer 1
#define R2_  8        // rows per block, layer 2
#define NCW_ 192      // layer-2 gate rows cached in smem
#define WS_  260      // smem weight row stride in floats (conflict-free)
#define NKQ_ 64       // 256 k / 4

// scratch (device globals; no allocation at runtime)
__device__ float g_out1[B_ * T_ * 100];      // layer-1 output [b][t][ch]
__device__ float g_Wcat[G2_ * KC_];          // packed rows [Whh2_f | Wih2_f | 0]
__device__ float g_WQ  [NKQ_ * GP_ * 4];     // k-quad-major: [kq][j][4]

__device__ __forceinline__ float sigf(float z) { return 1.0f / (1.0f + __expf(-z)); }
// overflow-safe fast tanh: e^{-2|x|} in (0,1], no inf/NaN; rel err ~1e-6
__device__ __forceinline__ float tanhfast(float x) {
    float t = __expf(-2.0f * fabsf(x));
    return copysignf((1.0f - t) / (1.0f + t), x);
}
__device__ __forceinline__ float lrelu(float z) { return z > 0.0f ? z : 0.3f * z; }

__device__ __forceinline__ unsigned long long pack2(float lo, float hi) {
    unsigned long long r;
    asm("mov.b64 %0, {%1, %2};" : "=l"(r) : "f"(lo), "f"(hi));
    return r;
}
__device__ __forceinline__ void fmaf2(unsigned long long& acc,
                                      unsigned long long a, unsigned long long b) {
    asm("fma.rn.f32x2 %0, %1, %2, %0;" : "+l"(acc) : "l"(a), "l"(b));
}
__device__ __forceinline__ float hsum2(unsigned long long v) {
    float lo, hi;
    asm("mov.b64 {%0, %1}, %2;" : "=f"(lo), "=f"(hi) : "l"(v));
    return lo + hi;
}

// ---------------------------------------------------------------------------
// K0: build g_Wcat (row-major, 256-wide) and g_WQ (k-quad-major, coalesced)
// ---------------------------------------------------------------------------
__global__ void prep_kernel(const float* __restrict__ Whh2f,
                            const float* __restrict__ Wih2f)
{
    int j = blockIdx.x;        // 608 blocks
    int k = threadIdx.x;       // 256 threads
    float v = 0.0f;
    if (j < G2_) {
        if (k < 150)       v = Whh2f[j * 150 + k];
        else if (k < 250)  v = Wih2f[j * 100 + (k - 150)];
        g_Wcat[j * KC_ + k] = v;
    }
    g_WQ[(k >> 2) * (GP_ * 4) + j * 4 + (k & 3)] = v;
}

// ---------------------------------------------------------------------------
// K1: layer-1 scan, both directions (blockIdx.y = dir), 8 rows per block.
// ---------------------------------------------------------------------------
__global__ void __launch_bounds__(256)
lstm1_kernel(const float* __restrict__ x,
             const float* __restrict__ Wih_f, const float* __restrict__ Whh_f,
             const float* __restrict__ b_f,
             const float* __restrict__ Wih_b, const float* __restrict__ Whh_b,
             const float* __restrict__ b_b)
{
    const int dir = blockIdx.y;
    const float* Wih = dir ? Wih_b : Wih_f;
    const float* Whh = dir ? Whh_b : Whh_f;
    const float* bv  = dir ? b_b  : b_f;
    const int row0 = blockIdx.x * R1_;
    const int tid  = threadIdx.x;

    __shared__ float h_s[R1_][H1_];     // row stride 200B: 8B-aligned pairs
    __shared__ float g_s[R1_][G1_];
    __shared__ float x_s[R1_][T_];

    for (int i = tid; i < R1_ * T_; i += 256)
        x_s[i / T_][i % T_] = x[(row0 + i / T_) * T_ + (i % T_)];
    for (int i = tid; i < R1_ * H1_; i += 256)
        h_s[i / H1_][i % H1_] = 0.0f;

    unsigned long long wp[H1_ / 2];
    float wih_j = 0.0f, bj = 0.0f;
    if (tid < G1_) {
#pragma unroll
        for (int kk = 0; kk < H1_ / 2; kk++) {
            float2 wv = *(const float2*)&Whh[tid * H1_ + 2 * kk];
            wp[kk] = pack2(wv.x, wv.y);
        }
        wih_j = Wih[tid];
        bj    = bv[tid];
    }

    const int u0 = tid, u1 = tid + 256;        // update items (r,k), total 400
    const int r0 = u0 / H1_, k0 = u0 % H1_;
    const int r1 = u1 / H1_, k1 = u1 % H1_;
    float c0 = 0.0f, c1 = 0.0f;

    __syncthreads();

    for (int t = 0; t < T_; t++) {
        const int tt = dir ? (T_ - 1 - t) : t;

        if (tid < G1_) {
            unsigned long long acc[R1_];
#pragma unroll
            for (int r = 0; r < R1_; r++)
                acc[r] = pack2(fmaf(x_s[r][tt], wih_j, bj), 0.0f);
#pragma unroll
            for (int kk = 0; kk < H1_ / 2; kk++) {
#pragma unroll
                for (int r = 0; r < R1_; r++) {
                    unsigned long long hv = *(const unsigned long long*)&h_s[r][2 * kk];
                    fmaf2(acc[r], wp[kk], hv);
                }
            }
#pragma unroll
            for (int r = 0; r < R1_; r++) g_s[r][tid] = hsum2(acc[r]);
        }
        __syncthreads();

        {
            float i_ = g_s[r0][k0], f_ = g_s[r0][H1_ + k0];
            float gg = g_s[r0][2 * H1_ + k0], o_ = g_s[r0][3 * H1_ + k0];
            c0 = sigf(f_) * c0 + sigf(i_) * tanhfast(gg);
            float h = sigf(o_) * tanhfast(c0);
            h_s[r0][k0] = h;
            g_out1[(row0 + r0) * (T_ * 100) + tt * 100 + dir * H1_ + k0] = h;
        }
        if (u1 < 400) {
            float i_ = g_s[r1][k1], f_ = g_s[r1][H1_ + k1];
            float gg = g_s[r1][2 * H1_ + k1], o_ = g_s[r1][3 * H1_ + k1];
            c1 = sigf(f_) * c1 + sigf(i_) * tanhfast(gg);
            float h = sigf(o_) * tanhfast(c1);
            h_s[r1][k1] = h;
            g_out1[(row0 + r1) * (T_ * 100) + tt * 100 + dir * H1_ + k1] = h;
        }
        __syncthreads();
    }
}

// ---------------------------------------------------------------------------
// K2: layer-2 FORWARD scan + fused backward-step + heads.
//   128 blocks x 608 threads, 8 rows per block.
// ---------------------------------------------------------------------------
#define SMEM2_BYTES ((NCW_ * WS_ + R2_ * KC_ + R2_ * GP_) * 4)   // 227,328 B

__global__ void __launch_bounds__(608, 1)
lstm2_kernel(const float* __restrict__ b2,
             const float* __restrict__ Wih2b, const float* __restrict__ b2b,
             const float* __restrict__ rrs,
             const float* __restrict__ headW, const float* __restrict__ headb,
             const float* __restrict__ p1W,  const float* __restrict__ p1b,
             const float* __restrict__ p2W,  const float* __restrict__ p2b,
             const float* __restrict__ fcW,  const float* __restrict__ fcb,
             float* __restrict__ out)
{
    extern __shared__ float sm[];
    float* w_c = sm;                                         // NCW_ * WS_
    float (*v_s)[KC_] = (float(*)[KC_])(sm + NCW_ * WS_);    // 8 x 256
    float (*g_s)[GP_] = (float(*)[GP_])(sm + NCW_ * WS_ + R2_ * KC_);

    const int tid  = threadIdx.x;
    const int row0 = blockIdx.x * R2_;

    for (int i = tid; i < NCW_ * KC_; i += 608)
        w_c[(i >> 8) * WS_ + (i & 255)] = g_Wcat[i];
    for (int i = tid; i < R2_ * KC_; i += 608)
        ((float*)v_s)[i] = 0.0f;

    const int j  = tid;                       // gate (608, last 8 dummy)
    const float bj = (j < G2_) ? b2[j] : 0.0f;

    const int u0 = tid, u1 = tid + 608;       // update items, total 1200
    const int r0 = u0 / H2_, k0 = u0 % H2_;
    const int r1 = u1 / H2_, k1 = u1 % H2_;
    float c0 = 0.0f, c1 = 0.0f;

    // hoisted x-prefetch addressing: 800 items, item A = tid (<800 always),
    // item B = tid + 608 (valid for tid < 192)
    const int pa_r = tid / 100, pa_c = tid % 100;
    const float* pa_src = g_out1 + (row0 + pa_r) * (T_ * 100) + pa_c;
    float* pa_dst = &v_s[pa_r][150 + pa_c];
    const bool pb_ok = (tid < 192);
    const int pb_r = (tid + 608) / 100, pb_c = (tid + 608) % 100;
    const float* pb_src = g_out1 + (row0 + pb_r) * (T_ * 100) + pb_c;
    float* pb_dst = &v_s[pb_r][150 + pb_c];

    __syncthreads();
    // prologue: x(t=0)
    *pa_dst = pa_src[0];
    if (pb_ok) *pb_dst = pb_src[0];
    __syncthreads();

    const float4* wq = (const float4*)g_WQ + j;          // stride GP_ per kq
    const ulonglong2* wsm = (const ulonglong2*)(w_c + j * WS_);

    for (int t = 0; t < T_; t++) {
        {
            unsigned long long acc[R2_];
#pragma unroll
            for (int r = 0; r < R2_; r++) acc[r] = pack2(bj, 0.0f);

            if (j < NCW_) {
#pragma unroll 4
                for (int kq = 0; kq < NKQ_; kq++) {
                    ulonglong2 w = wsm[kq];
#pragma unroll
                    for (int r = 0; r < R2_; r++) {
                        ulonglong2 v = *(const ulonglong2*)&v_s[r][kq * 4];
                        fmaf2(acc[r], w.x, v.x);
                        fmaf2(acc[r], w.y, v.y);
                    }
                }
            } else {
#pragma unroll 4
                for (int kq = 0; kq < NKQ_; kq++) {
                    float4 wf = wq[kq * GP_];            // coalesced LDG.128
                    ulonglong2 w = *(const ulonglong2*)&wf;
#pragma unroll
                    for (int r = 0; r < R2_; r++) {
                        ulonglong2 v = *(const ulonglong2*)&v_s[r][kq * 4];
                        fmaf2(acc[r], w.x, v.x);
                        fmaf2(acc[r], w.y, v.y);
                    }
                }
            }
#pragma unroll
            for (int r = 0; r < R2_; r++) g_s[r][j] = hsum2(acc[r]);
        }
        __syncthreads();

        {
            float i_ = g_s[r0][k0],            f_ = g_s[r0][H2_ + k0];
            float gg = g_s[r0][2 * H2_ + k0],  o_ = g_s[r0][3 * H2_ + k0];
            c0 = sigf(f_) * c0 + sigf(i_) * tanhfast(gg);
            v_s[r0][k0] = sigf(o_) * tanhfast(c0);
        }
        if (u1 < R2_ * H2_) {
            float i_ = g_s[r1][k1],            f_ = g_s[r1][H2_ + k1];
            float gg = g_s[r1][2 * H2_ + k1],  o_ = g_s[r1][3 * H2_ + k1];
            c1 = sigf(f_) * c1 + sigf(i_) * tanhfast(gg);
            v_s[r1][k1] = sigf(o_) * tanhfast(c1);
        }
        if (t < T_ - 1) {   // prefetch x(t+1): lanes 150..249, disjoint from h
            int off = (t + 1) * 100;
            *pa_dst = pa_src[off];
            if (pb_ok) *pb_dst = pb_src[off];
        }
        __syncthreads();
    }

    // ------------------------------------------------------------------
    // FUSED EPILOGUE.  v_s[r][0:150] = h2f(127); v_s[r][150:250] = out1[:,127]
    // ------------------------------------------------------------------
    // 1) backward gates (one step from h0=0 — Whh2b unused)
    if (j < G2_) {
        float acc[R2_];
#pragma unroll
        for (int r = 0; r < R2_; r++) acc[r] = b2b[j];
        const float2* wb = (const float2*)(Wih2b + j * 100);   // 8B-aligned
#pragma unroll 5
        for (int kh = 0; kh < 50; kh++) {
            float2 w = wb[kh];
#pragma unroll
            for (int r = 0; r < R2_; r++) {
                float2 v = *(const float2*)&v_s[r][150 + kh * 2];  // 8B-aligned
                acc[r] = fmaf(w.x, v.x, fmaf(w.y, v.y, acc[r]));
            }
        }
#pragma unroll
        for (int r = 0; r < R2_; r++) g_s[r][j] = acc[r];
    }
    __syncthreads();

    // 2) h2b + assemble net[r][300] = [h2f | h2b] (reuse weight-cache smem)
    float (*net_s)[304] = (float(*)[304])w_c;       // 8*304 floats << NCW_*WS_
    for (int i = tid; i < R2_ * H2_; i += 608) {
        int r = i / H2_, k = i % H2_;
        float i_ = g_s[r][k], gg = g_s[r][2 * H2_ + k], o_ = g_s[r][3 * H2_ + k];
        float c = sigf(i_) * tanhfast(gg);          // sig(f)*c0 term = 0
        net_s[r][150 + k] = sigf(o_) * tanhfast(c);
        net_s[r][k]       = v_s[r][k];
    }
    __syncthreads();

    // 3) heads.  feat[r][32] scratch in g_s space.
    float* feat = (float*)g_s;
    if (tid < 160) {                                // waveform: 8 rows x 20
        int r = tid / 20, o = tid % 20;
        float a = headb[o];
        const float2* hw = (const float2*)(headW + o * 300);
#pragma unroll 10
        for (int kh = 0; kh < 150; kh++) {
            float2 w = hw[kh];
            float2 v = *(const float2*)&net_s[r][kh * 2];
            a = fmaf(w.x, v.x, fmaf(w.y, v.y, a));
        }
        a = lrelu(a);
        feat[r * 32 + o] = a;
        out[(row0 + r) * 20 + o] = a;               // waveform_feat
    }
    if (tid >= 160 && tid < 240) {                  // pef: 8 rows x 10
        int t2 = tid - 160, r = t2 / 10, o = t2 % 10;
        float a = p1b[o];
#pragma unroll
        for (int k = 0; k < 4; k++) a = fmaf(p1W[o * 4 + k], rrs[(row0 + r) * 4 + k], a);
        feat[r * 32 + 20 + o] = lrelu(a);
    }
    __syncthreads();

    if (tid < 16) {                                 // pef_logits: 8 rows x 2
        int r = tid / 2, o = tid % 2;
        float a = p2b[o];
#pragma unroll
        for (int k = 0; k < 10; k++) a = fmaf(p2W[o * 10 + k], feat[r * 32 + 20 + k], a);
        out[B_ * 20 + (row0 + r) * 2 + o] = a;
    }
    if (tid >= 32 && tid < 272) {                   // feat out: 8 rows x 30
        int t2 = tid - 32, r = t2 / 30, o = t2 % 30;
        out[B_ * 22 + (row0 + r) * 30 + o] = feat[r * 32 + o];
    }
    if (tid >= 288 && tid < 320) {                  // logits: 8 rows x 4
        int t2 = tid - 288, r = t2 / 4, o = t2 % 4;
        float a = fcb[o];
#pragma unroll
        for (int k = 0; k < 30; k++) a = fmaf(fcW[o * 30 + k], feat[r * 32 + k], a);
        out[B_ * 52 + (row0 + r) * 4 + o] = a;
    }
}

// ---------------------------------------------------------------------------
extern "C" void kernel_launch(void* const* d_in, const int* in_sizes, int n_in,
                              void* d_out, int out_size)
{
    const float* x      = (const float*)d_in[0];
    const float* rrs    = (const float*)d_in[1];
    const float* l1Wihf = (const float*)d_in[2];
    const float* l1Whhf = (const float*)d_in[3];
    const float* l1bf   = (const float*)d_in[4];
    const float* l1Wihb = (const float*)d_in[5];
    const float* l1Whhb = (const float*)d_in[6];
    const float* l1bb   = (const float*)d_in[7];
    const float* l2Wihf = (const float*)d_in[8];
    const float* l2Whhf = (const float*)d_in[9];
    const float* l2bf   = (const float*)d_in[10];
    const float* l2Wihb = (const float*)d_in[11];
    /* d_in[12] = l2_Whh_b: unused — backward L2 is a single step from h0=0 */
    const float* l2bb   = (const float*)d_in[13];
    const float* headW  = (const float*)d_in[14];
    const float* headb  = (const float*)d_in[15];
    const float* p1W    = (const float*)d_in[16];
    const float* p1b    = (const float*)d_in[17];
    const float* p2W    = (const float*)d_in[18];
    const float* p2b    = (const float*)d_in[19];
    const float* fcW    = (const float*)d_in[20];
    const float* fcb    = (const float*)d_in[21];

    cudaFuncSetAttribute(lstm2_kernel,
                         cudaFuncAttributeMaxDynamicSharedMemorySize, SMEM2_BYTES);

    prep_kernel<<<GP_, KC_>>>(l2Whhf, l2Wihf);
    lstm1_kernel<<<dim3(B_ / R1_, 2), 256>>>(x, l1Wihf, l1Whhf, l1bf,
                                             l1Wihb, l1Whhb, l1bb);
    lstm2_kernel<<<B_ / R2_, 608, SMEM2_BYTES>>>(l2bf, l2Wihb, l2bb, rrs,
                                                 headW, headb, p1W, p1b,
                                                 p2W, p2b, fcW, fcb,
                                                 (float*)d_out);
}